// round 3
// baseline (speedup 1.0000x reference)
#include <cuda_runtime.h>
#include <cuda_bf16.h>

// NonSparsePLIF: v[t] = where(v[t-1]*d + x[t] >= 1.0, 0, v[t-1]*d + x[t])
// x_seq [T=16, 4194304] f32, decay [1] f32. HBM-bound streaming scan.
// R3: persistent grid-stride (grid = 148 SMs * 8 CTA = 1184) -> no wave
// transitions, flat tail. Plain loads/stores (hints measured neutral/worse).

#define T_STEPS 16
#define SPATIAL 4194304            // 16*64*64*64
#define SPATIAL4 (SPATIAL / 4)     // 1048576 float4 per timestep plane
#define THREADS 256
#define NUM_SMS 148
#define CTAS_PER_SM 8
#define VTH 1.0f

__global__ __launch_bounds__(THREADS) void plif_kernel(
    const float4* __restrict__ x,      // [T, SPATIAL4]
    const float* __restrict__ decay,   // [1]
    float4* __restrict__ out)          // [T, SPATIAL4]
{
    const float d = decay[0];
    const int stride = gridDim.x * THREADS;

    for (int i = blockIdx.x * THREADS + threadIdx.x; i < SPATIAL4; i += stride) {
        float4 v = make_float4(0.f, 0.f, 0.f, 0.f);

#pragma unroll
        for (int t = 0; t < T_STEPS; ++t) {
            const size_t idx = (size_t)t * SPATIAL4 + i;
            const float4 xt = x[idx];
            v.x = fmaf(v.x, d, xt.x);
            v.y = fmaf(v.y, d, xt.y);
            v.z = fmaf(v.z, d, xt.z);
            v.w = fmaf(v.w, d, xt.w);
            v.x = (v.x >= VTH) ? 0.f : v.x;
            v.y = (v.y >= VTH) ? 0.f : v.y;
            v.z = (v.z >= VTH) ? 0.f : v.z;
            v.w = (v.w >= VTH) ? 0.f : v.w;
            out[idx] = v;
        }
    }
}

extern "C" void kernel_launch(void* const* d_in, const int* in_sizes, int n_in,
                              void* d_out, int out_size)
{
    const float4* x   = (const float4*)d_in[0];
    const float*  dec = (const float*)d_in[1];
    float4*       out = (float4*)d_out;

    const int blocks = NUM_SMS * CTAS_PER_SM;  // 1184 persistent CTAs
    plif_kernel<<<blocks, THREADS>>>(x, dec, out);
}

// round 4
// speedup vs baseline: 1.0213x; 1.0213x over previous
#include <cuda_runtime.h>
#include <cuda_bf16.h>

// NonSparsePLIF: v[t] = where(v[t-1]*d + x[t] >= 1.0, 0, v[t-1]*d + x[t])
// x_seq [T=16, 4194304] f32, decay [1] f32. HBM-bound streaming scan.
// R4: R1's winning shape (1 float4/thread, grid=4096) + __stcs store hint only
// (R2 showed ldcs+stcs together neutral; isolating the store-side hint).

#define T_STEPS 16
#define SPATIAL 4194304            // 16*64*64*64
#define SPATIAL4 (SPATIAL / 4)     // float4 elements per timestep plane
#define VTH 1.0f

__global__ __launch_bounds__(256) void plif_kernel(
    const float4* __restrict__ x,      // [T, SPATIAL4]
    const float* __restrict__ decay,   // [1]
    float4* __restrict__ out)          // [T, SPATIAL4]
{
    const int i = blockIdx.x * blockDim.x + threadIdx.x;
    if (i >= SPATIAL4) return;

    const float d = decay[0];

    float4 v = make_float4(0.f, 0.f, 0.f, 0.f);

#pragma unroll
    for (int t = 0; t < T_STEPS; ++t) {
        const size_t idx = (size_t)t * SPATIAL4 + i;
        const float4 xt = x[idx];
        v.x = fmaf(v.x, d, xt.x);
        v.y = fmaf(v.y, d, xt.y);
        v.z = fmaf(v.z, d, xt.z);
        v.w = fmaf(v.w, d, xt.w);
        v.x = (v.x >= VTH) ? 0.f : v.x;
        v.y = (v.y >= VTH) ? 0.f : v.y;
        v.z = (v.z >= VTH) ? 0.f : v.z;
        v.w = (v.w >= VTH) ? 0.f : v.w;
        __stcs(&out[idx], v);   // write-once output: evict-first in L2
    }
}

extern "C" void kernel_launch(void* const* d_in, const int* in_sizes, int n_in,
                              void* d_out, int out_size)
{
    const float4* x   = (const float4*)d_in[0];
    const float*  dec = (const float*)d_in[1];
    float4*       out = (float4*)d_out;

    const int threads = 256;
    const int blocks  = (SPATIAL4 + threads - 1) / threads;  // 4096
    plif_kernel<<<blocks, threads>>>(x, dec, out);
}

// round 5
// speedup vs baseline: 1.0225x; 1.0011x over previous
#include <cuda_runtime.h>
#include <cuda_bf16.h>

// NonSparsePLIF: v[t] = where(v[t-1]*d + x[t] >= 1.0, 0, v[t-1]*d + x[t])
// x_seq [T=16, 4194304] f32, decay [1] f32. HBM-bound streaming scan.
// R5: R4 (best: 76.45us, DRAM 79.8%) with block=128 / 8192 CTAs — finer
// scheduling quanta for smoother wave tails. Expected neutral; this kernel
// is at the mixed-RW HBM roofline (512 MB mandatory traffic @ ~6.3 TB/s).

#define T_STEPS 16
#define SPATIAL 4194304            // 16*64*64*64
#define SPATIAL4 (SPATIAL / 4)     // float4 elements per timestep plane
#define THREADS 128
#define VTH 1.0f

__global__ __launch_bounds__(THREADS) void plif_kernel(
    const float4* __restrict__ x,      // [T, SPATIAL4]
    const float* __restrict__ decay,   // [1]
    float4* __restrict__ out)          // [T, SPATIAL4]
{
    const int i = blockIdx.x * THREADS + threadIdx.x;
    if (i >= SPATIAL4) return;

    const float d = decay[0];

    float4 v = make_float4(0.f, 0.f, 0.f, 0.f);

#pragma unroll
    for (int t = 0; t < T_STEPS; ++t) {
        const size_t idx = (size_t)t * SPATIAL4 + i;
        const float4 xt = x[idx];
        v.x = fmaf(v.x, d, xt.x);
        v.y = fmaf(v.y, d, xt.y);
        v.z = fmaf(v.z, d, xt.z);
        v.w = fmaf(v.w, d, xt.w);
        v.x = (v.x >= VTH) ? 0.f : v.x;
        v.y = (v.y >= VTH) ? 0.f : v.y;
        v.z = (v.z >= VTH) ? 0.f : v.z;
        v.w = (v.w >= VTH) ? 0.f : v.w;
        __stcs(&out[idx], v);   // write-once output: evict-first in L2
    }
}

extern "C" void kernel_launch(void* const* d_in, const int* in_sizes, int n_in,
                              void* d_out, int out_size)
{
    const float4* x   = (const float4*)d_in[0];
    const float*  dec = (const float*)d_in[1];
    float4*       out = (float4*)d_out;

    const int blocks = (SPATIAL4 + THREADS - 1) / THREADS;  // 8192
    plif_kernel<<<blocks, THREADS>>>(x, dec, out);
}